// round 2
// baseline (speedup 1.0000x reference)
#include <cuda_runtime.h>
#include <math.h>

// ---------------------------------------------------------------------------
// Problem constants
// ---------------------------------------------------------------------------
#define BATCH   16384
#define MOTW    256      // motions width = MOTION*(USED-1)
#define LAT     32
#define IN_DIM  288      // MOTW + LAT
#define H1      512
#define H2      512
#define MOE     8
#define MOTION  128
#define KC2     544      // H1 + LAT
#define KC3     544      // H2 + LAT

// ---------------------------------------------------------------------------
// Scratch (device globals; no allocation allowed)
// ---------------------------------------------------------------------------
__device__ float d_x   [(long)BATCH * IN_DIM];        // concat(motions, z)
__device__ float d_g1  [(long)BATCH * H1];            // gate hidden 1
__device__ float d_g2  [(long)BATCH * H2];            // gate hidden 2
__device__ float d_para[(long)BATCH * MOE];           // gate output
__device__ float d_norm2;                             // sum of para^2
__device__ float d_h1  [(long)MOE * BATCH * H1];      // expert layer-1 out
__device__ float d_h2  [(long)MOE * BATCH * H2];      // expert layer-2 out
__device__ float d_h3  [(long)MOE * BATCH * MOTION];  // expert layer-3 out

__device__ __forceinline__ float elu1(float v) {
    return v > 0.f ? v : expm1f(v);
}

// ---------------------------------------------------------------------------
// K0: build x = concat(motions, z), and reset norm2 accumulator
// ---------------------------------------------------------------------------
__global__ void build_x_kernel(const float* __restrict__ motions,
                               const float* __restrict__ z,
                               float* __restrict__ x) {
    int i = blockIdx.x * blockDim.x + threadIdx.x;
    if (i == 0) d_norm2 = 0.f;   // graph replays re-run this -> always reset
    if (i < BATCH * IN_DIM) {
        int b = i / IN_DIM;
        int c = i - b * IN_DIM;
        x[i] = (c < MOTW) ? motions[b * MOTW + c] : z[b * LAT + (c - MOTW)];
    }
}

// ---------------------------------------------------------------------------
// Generic tiled GEMM + bias + ELU.
//   C[row, n] = ELU( sum_k A(row,k) * W[k,n] + bias[n] )
// A is logically the concat [A1 (width K1) | A2 (width LAT)]; A2 may be null.
// K1 and (K-K1) are multiples of BK=8, so each k-tile has a single source.
// grid.z = expert index; per-expert strides passed in.
// BM = BN = 128, BK = 8, 256 threads, 8x8 per-thread tile.
// ---------------------------------------------------------------------------
__global__ __launch_bounds__(256) void gemm_elu_kernel(
    const float* __restrict__ A1, int K1,
    const float* __restrict__ A2,                // width LAT rows, or null
    const float* __restrict__ W,                 // [K, N] row-major
    const float* __restrict__ bias,              // [N]
    float* __restrict__ C,                       // [B, N] row-major
    int K, int N,
    long sA1, long sW, int sBias, long sC)
{
    const int e = blockIdx.z;
    A1   += (long)e * sA1;
    W    += (long)e * sW;
    bias += (long)e * sBias;
    C    += (long)e * sC;

    __shared__ float As[8][128];   // [k][row]
    __shared__ float Bs[8][128];   // [k][col]

    const int tid = threadIdx.x;
    const int tx  = tid & 15;      // 0..15 -> col groups
    const int ty  = tid >> 4;      // 0..15 -> row groups
    const int rowBase = blockIdx.y * 128;
    const int colBase = blockIdx.x * 128;

    // A-tile load mapping: 128 rows x 8 cols = 256 float4
    const int arow = tid >> 1;           // 0..127
    const int aseg = (tid & 1) * 4;      // 0 or 4
    // B-tile load mapping: 8 rows x 128 cols = 256 float4
    const int bk   = tid >> 5;           // 0..7
    const int bseg = (tid & 31) * 4;     // 0..124

    float acc[8][8];
#pragma unroll
    for (int i = 0; i < 8; ++i)
#pragma unroll
        for (int j = 0; j < 8; ++j) acc[i][j] = 0.f;

    const int nKT = K >> 3;
    for (int kt = 0; kt < nKT; ++kt) {
        const int k0 = kt << 3;

        // ---- load A tile (source select per k-tile; boundaries are aligned)
        const float* src;
        int ld, kk;
        if (k0 < K1) { src = A1; ld = K1;  kk = k0 + aseg; }
        else         { src = A2; ld = LAT; kk = k0 - K1 + aseg; }
        float4 av = *(const float4*)(src + (long)(rowBase + arow) * ld + kk);
        As[aseg + 0][arow] = av.x;
        As[aseg + 1][arow] = av.y;
        As[aseg + 2][arow] = av.z;
        As[aseg + 3][arow] = av.w;

        // ---- load B tile (coalesced float4)
        float4 bv = *(const float4*)(W + (long)(k0 + bk) * N + colBase + bseg);
        *(float4*)&Bs[bk][bseg] = bv;

        __syncthreads();

#pragma unroll
        for (int k = 0; k < 8; ++k) {
            float a[8], b[8];
            *(float4*)&a[0] = *(const float4*)&As[k][ty * 8];
            *(float4*)&a[4] = *(const float4*)&As[k][ty * 8 + 4];
            *(float4*)&b[0] = *(const float4*)&Bs[k][tx * 8];
            *(float4*)&b[4] = *(const float4*)&Bs[k][tx * 8 + 4];
#pragma unroll
            for (int i = 0; i < 8; ++i)
#pragma unroll
                for (int j = 0; j < 8; ++j)
                    acc[i][j] = fmaf(a[i], b[j], acc[i][j]);
        }
        __syncthreads();
    }

    // ---- epilogue: bias + ELU, float4 stores
    float bvals[8];
#pragma unroll
    for (int j = 0; j < 8; ++j) bvals[j] = bias[colBase + tx * 8 + j];

#pragma unroll
    for (int i = 0; i < 8; ++i) {
        const int row = rowBase + ty * 8 + i;
        float* crow = C + (long)row * N + colBase + tx * 8;
        float4 v0, v1;
        v0.x = elu1(acc[i][0] + bvals[0]);
        v0.y = elu1(acc[i][1] + bvals[1]);
        v0.z = elu1(acc[i][2] + bvals[2]);
        v0.w = elu1(acc[i][3] + bvals[3]);
        v1.x = elu1(acc[i][4] + bvals[4]);
        v1.y = elu1(acc[i][5] + bvals[5]);
        v1.z = elu1(acc[i][6] + bvals[6]);
        v1.w = elu1(acc[i][7] + bvals[7]);
        *(float4*)(crow)     = v0;
        *(float4*)(crow + 4) = v1;
    }
}

// ---------------------------------------------------------------------------
// Gate layer 3: para[b,e] = ELU( g2[b,:] @ gw3[:,e] + gb3[e] ),  N = 8
// One thread per (row, e); gw3 staged in SMEM.
// ---------------------------------------------------------------------------
__global__ __launch_bounds__(256) void gate3_kernel(
    const float* __restrict__ g2,
    const float* __restrict__ gw3,   // [512, 8]
    const float* __restrict__ gb3,   // [8]
    float* __restrict__ para)
{
    __shared__ float w[H2 * MOE];    // 16 KB
    const int tid = threadIdx.x;
    for (int i = tid; i < H2 * MOE; i += 256) w[i] = gw3[i];
    __syncthreads();

    const int e = tid & 7;
    const int r = tid >> 3;          // 0..31
    const int row = blockIdx.x * 32 + r;
    const float* grow = g2 + (long)row * H2;

    float s0 = gb3[e], s1 = 0.f;
#pragma unroll 4
    for (int k = 0; k < H2; k += 2) {
        s0 = fmaf(grow[k],     w[k * 8 + e],       s0);
        s1 = fmaf(grow[k + 1], w[(k + 1) * 8 + e], s1);
    }
    para[(long)row * MOE + e] = elu1(s0 + s1);
}

// ---------------------------------------------------------------------------
// Frobenius-norm reduction: d_norm2 += sum(para^2)
// ---------------------------------------------------------------------------
__global__ void norm_reduce_kernel(const float* __restrict__ para) {
    float s = 0.f;
    for (long i = blockIdx.x * blockDim.x + threadIdx.x;
         i < (long)BATCH * MOE; i += (long)gridDim.x * blockDim.x) {
        float v = para[i];
        s = fmaf(v, v, s);
    }
#pragma unroll
    for (int o = 16; o > 0; o >>= 1) s += __shfl_xor_sync(0xFFFFFFFFu, s, o);
    if ((threadIdx.x & 31) == 0) atomicAdd(&d_norm2, s);
}

// ---------------------------------------------------------------------------
// Combine: out[b,m] = sigmoid( rsqrt(norm2) * sum_e para[b,e]*h3[e,b,m] )
// ---------------------------------------------------------------------------
__global__ __launch_bounds__(256) void combine_kernel(
    const float* __restrict__ para,
    const float* __restrict__ h3,
    float* __restrict__ out)
{
    const int i = blockIdx.x * 256 + threadIdx.x;   // b*128 + m
    const int b = i >> 7;
    const int m = i & 127;
    const float inv = rsqrtf(d_norm2);

    float s = 0.f;
#pragma unroll
    for (int e = 0; e < MOE; ++e)
        s = fmaf(para[(long)b * MOE + e],
                 h3[((long)e * BATCH + b) * MOTION + m], s);
    s *= inv;
    out[i] = 1.f / (1.f + expf(-s));
}

// ---------------------------------------------------------------------------
// Launch pipeline (graph-capturable: kernels only, default stream)
// ---------------------------------------------------------------------------
extern "C" void kernel_launch(void* const* d_in, const int* in_sizes, int n_in,
                              void* d_out, int out_size) {
    const float* motions = (const float*)d_in[0];
    const float* z       = (const float*)d_in[1];
    const float* gw1     = (const float*)d_in[2];
    const float* gb1     = (const float*)d_in[3];
    const float* gw2     = (const float*)d_in[4];
    const float* gb2     = (const float*)d_in[5];
    const float* gw3     = (const float*)d_in[6];
    const float* gb3     = (const float*)d_in[7];
    const float* W1      = (const float*)d_in[8];
    const float* b1      = (const float*)d_in[9];
    const float* W2      = (const float*)d_in[10];
    const float* b2      = (const float*)d_in[11];
    const float* W3      = (const float*)d_in[12];
    const float* b3      = (const float*)d_in[13];
    float* out = (float*)d_out;

    void *px, *pg1, *pg2, *ppara, *ph1, *ph2, *ph3;
    cudaGetSymbolAddress(&px,    d_x);
    cudaGetSymbolAddress(&pg1,   d_g1);
    cudaGetSymbolAddress(&pg2,   d_g2);
    cudaGetSymbolAddress(&ppara, d_para);
    cudaGetSymbolAddress(&ph1,   d_h1);
    cudaGetSymbolAddress(&ph2,   d_h2);
    cudaGetSymbolAddress(&ph3,   d_h3);

    float* x    = (float*)px;
    float* g1   = (float*)pg1;
    float* g2   = (float*)pg2;
    float* para = (float*)ppara;
    float* h1   = (float*)ph1;
    float* h2   = (float*)ph2;
    float* h3   = (float*)ph3;

    // 0) concat input (+ reset norm2)
    build_x_kernel<<<(BATCH * IN_DIM + 255) / 256, 256>>>(motions, z, x);

    // 1) gate MLP
    gemm_elu_kernel<<<dim3(H1 / 128, BATCH / 128, 1), 256>>>(
        x, IN_DIM, nullptr, gw1, gb1, g1, IN_DIM, H1, 0, 0, 0, 0);
    gemm_elu_kernel<<<dim3(H2 / 128, BATCH / 128, 1), 256>>>(
        g1, H1, nullptr, gw2, gb2, g2, H1, H2, 0, 0, 0, 0);
    gate3_kernel<<<BATCH / 32, 256>>>(g2, gw3, gb3, para);
    norm_reduce_kernel<<<256, 256>>>(para);

    // 2) experts (grid.z = expert)
    gemm_elu_kernel<<<dim3(H1 / 128, BATCH / 128, MOE), 256>>>(
        x, IN_DIM, nullptr, W1, b1, h1, IN_DIM, H1,
        0, (long)IN_DIM * H1, H1, (long)BATCH * H1);
    gemm_elu_kernel<<<dim3(H2 / 128, BATCH / 128, MOE), 256>>>(
        h1, H1, z, W2, b2, h2, KC2, H2,
        (long)BATCH * H1, (long)KC2 * H2, H2, (long)BATCH * H2);
    gemm_elu_kernel<<<dim3(MOTION / 128, BATCH / 128, MOE), 256>>>(
        h2, H2, z, W3, b3, h3, KC3, MOTION,
        (long)BATCH * H2, (long)KC3 * MOTION, MOTION, (long)BATCH * MOTION);

    // 3) gated combine + norm + sigmoid
    combine_kernel<<<BATCH * MOTION / 256, 256>>>(para, h3, out);
}

// round 3
// speedup vs baseline: 1.0003x; 1.0003x over previous
#include <cuda_runtime.h>
#include <math.h>

// ---------------------------------------------------------------------------
// Problem constants
// ---------------------------------------------------------------------------
#define BATCH   16384
#define MOTW    256      // motions width = MOTION*(USED-1)
#define LAT     32
#define IN_DIM  288      // MOTW + LAT
#define H1      512
#define H2      512
#define MOE     8
#define MOTION  128
#define KC2     544      // H1 + LAT
#define KC3     544      // H2 + LAT

// ---------------------------------------------------------------------------
// Scratch (device globals; no allocation allowed)
// ---------------------------------------------------------------------------
__device__ float d_x   [(long)BATCH * IN_DIM];        // concat(motions, z)
__device__ float d_g1  [(long)BATCH * H1];            // gate hidden 1
__device__ float d_g2  [(long)BATCH * H2];            // gate hidden 2
__device__ float d_para[(long)BATCH * MOE];           // gate output
__device__ float d_norm2;                             // sum of para^2
__device__ float d_h1  [(long)MOE * BATCH * H1];      // expert layer-1 out
__device__ float d_h2  [(long)MOE * BATCH * H2];      // expert layer-2 out
__device__ float d_h3  [(long)MOE * BATCH * MOTION];  // expert layer-3 out

__device__ __forceinline__ float elu1(float v) {
    return v > 0.f ? v : expm1f(v);
}

// ---------------------------------------------------------------------------
// K0: build x = concat(motions, z), and reset norm2 accumulator
// ---------------------------------------------------------------------------
__global__ void build_x_kernel(const float* __restrict__ motions,
                               const float* __restrict__ z,
                               float* __restrict__ x) {
    int i = blockIdx.x * blockDim.x + threadIdx.x;
    if (i == 0) d_norm2 = 0.f;   // graph replays re-run this -> always reset
    if (i < BATCH * IN_DIM) {
        int b = i / IN_DIM;
        int c = i - b * IN_DIM;
        x[i] = (c < MOTW) ? motions[b * MOTW + c] : z[b * LAT + (c - MOTW)];
    }
}

// ---------------------------------------------------------------------------
// Generic tiled GEMM + bias + ELU.
//   C[row, n] = ELU( sum_k A(row,k) * W[k,n] + bias[n] )
// A is logically the concat [A1 (width K1) | A2 (width LAT)]; A2 may be null.
// K1 and (K-K1) are multiples of BK=8, so each k-tile has a single source.
// grid.z = expert index; per-expert strides passed in.
// BM = BN = 128, BK = 8, 256 threads, 8x8 per-thread tile.
// ---------------------------------------------------------------------------
__global__ __launch_bounds__(256) void gemm_elu_kernel(
    const float* __restrict__ A1, int K1,
    const float* __restrict__ A2,                // width LAT rows, or null
    const float* __restrict__ W,                 // [K, N] row-major
    const float* __restrict__ bias,              // [N]
    float* __restrict__ C,                       // [B, N] row-major
    int K, int N,
    long sA1, long sW, int sBias, long sC)
{
    const int e = blockIdx.z;
    A1   += (long)e * sA1;
    W    += (long)e * sW;
    bias += (long)e * sBias;
    C    += (long)e * sC;

    __shared__ float As[8][128];   // [k][row]
    __shared__ float Bs[8][128];   // [k][col]

    const int tid = threadIdx.x;
    const int tx  = tid & 15;      // 0..15 -> col groups
    const int ty  = tid >> 4;      // 0..15 -> row groups
    const int rowBase = blockIdx.y * 128;
    const int colBase = blockIdx.x * 128;

    // A-tile load mapping: 128 rows x 8 cols = 256 float4
    const int arow = tid >> 1;           // 0..127
    const int aseg = (tid & 1) * 4;      // 0 or 4
    // B-tile load mapping: 8 rows x 128 cols = 256 float4
    const int bk   = tid >> 5;           // 0..7
    const int bseg = (tid & 31) * 4;     // 0..124

    float acc[8][8];
#pragma unroll
    for (int i = 0; i < 8; ++i)
#pragma unroll
        for (int j = 0; j < 8; ++j) acc[i][j] = 0.f;

    const int nKT = K >> 3;
    for (int kt = 0; kt < nKT; ++kt) {
        const int k0 = kt << 3;

        // ---- load A tile (source select per k-tile; boundaries are aligned)
        const float* src;
        int ld, kk;
        if (k0 < K1) { src = A1; ld = K1;  kk = k0 + aseg; }
        else         { src = A2; ld = LAT; kk = k0 - K1 + aseg; }
        float4 av = *(const float4*)(src + (long)(rowBase + arow) * ld + kk);
        As[aseg + 0][arow] = av.x;
        As[aseg + 1][arow] = av.y;
        As[aseg + 2][arow] = av.z;
        As[aseg + 3][arow] = av.w;

        // ---- load B tile (coalesced float4)
        float4 bv = *(const float4*)(W + (long)(k0 + bk) * N + colBase + bseg);
        *(float4*)&Bs[bk][bseg] = bv;

        __syncthreads();

#pragma unroll
        for (int k = 0; k < 8; ++k) {
            float a[8], b[8];
            *(float4*)&a[0] = *(const float4*)&As[k][ty * 8];
            *(float4*)&a[4] = *(const float4*)&As[k][ty * 8 + 4];
            *(float4*)&b[0] = *(const float4*)&Bs[k][tx * 8];
            *(float4*)&b[4] = *(const float4*)&Bs[k][tx * 8 + 4];
#pragma unroll
            for (int i = 0; i < 8; ++i)
#pragma unroll
                for (int j = 0; j < 8; ++j)
                    acc[i][j] = fmaf(a[i], b[j], acc[i][j]);
        }
        __syncthreads();
    }

    // ---- epilogue: bias + ELU, float4 stores
    float bvals[8];
#pragma unroll
    for (int j = 0; j < 8; ++j) bvals[j] = bias[colBase + tx * 8 + j];

#pragma unroll
    for (int i = 0; i < 8; ++i) {
        const int row = rowBase + ty * 8 + i;
        float* crow = C + (long)row * N + colBase + tx * 8;
        float4 v0, v1;
        v0.x = elu1(acc[i][0] + bvals[0]);
        v0.y = elu1(acc[i][1] + bvals[1]);
        v0.z = elu1(acc[i][2] + bvals[2]);
        v0.w = elu1(acc[i][3] + bvals[3]);
        v1.x = elu1(acc[i][4] + bvals[4]);
        v1.y = elu1(acc[i][5] + bvals[5]);
        v1.z = elu1(acc[i][6] + bvals[6]);
        v1.w = elu1(acc[i][7] + bvals[7]);
        *(float4*)(crow)     = v0;
        *(float4*)(crow + 4) = v1;
    }
}

// ---------------------------------------------------------------------------
// Gate layer 3: para[b,e] = ELU( g2[b,:] @ gw3[:,e] + gb3[e] ),  N = 8
// One thread per (row, e); gw3 staged in SMEM.
// ---------------------------------------------------------------------------
__global__ __launch_bounds__(256) void gate3_kernel(
    const float* __restrict__ g2,
    const float* __restrict__ gw3,   // [512, 8]
    const float* __restrict__ gb3,   // [8]
    float* __restrict__ para)
{
    __shared__ float w[H2 * MOE];    // 16 KB
    const int tid = threadIdx.x;
    for (int i = tid; i < H2 * MOE; i += 256) w[i] = gw3[i];
    __syncthreads();

    const int e = tid & 7;
    const int r = tid >> 3;          // 0..31
    const int row = blockIdx.x * 32 + r;
    const float* grow = g2 + (long)row * H2;

    float s0 = gb3[e], s1 = 0.f;
#pragma unroll 4
    for (int k = 0; k < H2; k += 2) {
        s0 = fmaf(grow[k],     w[k * 8 + e],       s0);
        s1 = fmaf(grow[k + 1], w[(k + 1) * 8 + e], s1);
    }
    para[(long)row * MOE + e] = elu1(s0 + s1);
}

// ---------------------------------------------------------------------------
// Frobenius-norm reduction: d_norm2 += sum(para^2)
// ---------------------------------------------------------------------------
__global__ void norm_reduce_kernel(const float* __restrict__ para) {
    float s = 0.f;
    for (long i = blockIdx.x * blockDim.x + threadIdx.x;
         i < (long)BATCH * MOE; i += (long)gridDim.x * blockDim.x) {
        float v = para[i];
        s = fmaf(v, v, s);
    }
#pragma unroll
    for (int o = 16; o > 0; o >>= 1) s += __shfl_xor_sync(0xFFFFFFFFu, s, o);
    if ((threadIdx.x & 31) == 0) atomicAdd(&d_norm2, s);
}

// ---------------------------------------------------------------------------
// Combine: out[b,m] = sigmoid( rsqrt(norm2) * sum_e para[b,e]*h3[e,b,m] )
// ---------------------------------------------------------------------------
__global__ __launch_bounds__(256) void combine_kernel(
    const float* __restrict__ para,
    const float* __restrict__ h3,
    float* __restrict__ out)
{
    const int i = blockIdx.x * 256 + threadIdx.x;   // b*128 + m
    const int b = i >> 7;
    const int m = i & 127;
    const float inv = rsqrtf(d_norm2);

    float s = 0.f;
#pragma unroll
    for (int e = 0; e < MOE; ++e)
        s = fmaf(para[(long)b * MOE + e],
                 h3[((long)e * BATCH + b) * MOTION + m], s);
    s *= inv;
    out[i] = 1.f / (1.f + expf(-s));
}

// ---------------------------------------------------------------------------
// Launch pipeline (graph-capturable: kernels only, default stream)
// ---------------------------------------------------------------------------
extern "C" void kernel_launch(void* const* d_in, const int* in_sizes, int n_in,
                              void* d_out, int out_size) {
    const float* motions = (const float*)d_in[0];
    const float* z       = (const float*)d_in[1];
    const float* gw1     = (const float*)d_in[2];
    const float* gb1     = (const float*)d_in[3];
    const float* gw2     = (const float*)d_in[4];
    const float* gb2     = (const float*)d_in[5];
    const float* gw3     = (const float*)d_in[6];
    const float* gb3     = (const float*)d_in[7];
    const float* W1      = (const float*)d_in[8];
    const float* b1      = (const float*)d_in[9];
    const float* W2      = (const float*)d_in[10];
    const float* b2      = (const float*)d_in[11];
    const float* W3      = (const float*)d_in[12];
    const float* b3      = (const float*)d_in[13];
    float* out = (float*)d_out;

    void *px, *pg1, *pg2, *ppara, *ph1, *ph2, *ph3;
    cudaGetSymbolAddress(&px,    d_x);
    cudaGetSymbolAddress(&pg1,   d_g1);
    cudaGetSymbolAddress(&pg2,   d_g2);
    cudaGetSymbolAddress(&ppara, d_para);
    cudaGetSymbolAddress(&ph1,   d_h1);
    cudaGetSymbolAddress(&ph2,   d_h2);
    cudaGetSymbolAddress(&ph3,   d_h3);

    float* x    = (float*)px;
    float* g1   = (float*)pg1;
    float* g2   = (float*)pg2;
    float* para = (float*)ppara;
    float* h1   = (float*)ph1;
    float* h2   = (float*)ph2;
    float* h3   = (float*)ph3;

    // 0) concat input (+ reset norm2)
    build_x_kernel<<<(BATCH * IN_DIM + 255) / 256, 256>>>(motions, z, x);

    // 1) gate MLP
    gemm_elu_kernel<<<dim3(H1 / 128, BATCH / 128, 1), 256>>>(
        x, IN_DIM, nullptr, gw1, gb1, g1, IN_DIM, H1, 0, 0, 0, 0);
    gemm_elu_kernel<<<dim3(H2 / 128, BATCH / 128, 1), 256>>>(
        g1, H1, nullptr, gw2, gb2, g2, H1, H2, 0, 0, 0, 0);
    gate3_kernel<<<BATCH / 32, 256>>>(g2, gw3, gb3, para);
    norm_reduce_kernel<<<256, 256>>>(para);

    // 2) experts (grid.z = expert)
    gemm_elu_kernel<<<dim3(H1 / 128, BATCH / 128, MOE), 256>>>(
        x, IN_DIM, nullptr, W1, b1, h1, IN_DIM, H1,
        0, (long)IN_DIM * H1, H1, (long)BATCH * H1);
    gemm_elu_kernel<<<dim3(H2 / 128, BATCH / 128, MOE), 256>>>(
        h1, H1, z, W2, b2, h2, KC2, H2,
        (long)BATCH * H1, (long)KC2 * H2, H2, (long)BATCH * H2);
    gemm_elu_kernel<<<dim3(MOTION / 128, BATCH / 128, MOE), 256>>>(
        h2, H2, z, W3, b3, h3, KC3, MOTION,
        (long)BATCH * H2, (long)KC3 * MOTION, MOTION, (long)BATCH * MOTION);

    // 3) gated combine + norm + sigmoid
    combine_kernel<<<BATCH * MOTION / 256, 256>>>(para, h3, out);
}